// round 16
// baseline (speedup 1.0000x reference)
#include <cuda_runtime.h>
#include <cuda_bf16.h>

#define NUM_GENES 20000
#define NUM_FEAT  256
#define BATCH     32
#define VOCAB     9
#define F4_PER_ROW (NUM_FEAT / 4)               // 64 float4 per row
#define GENES_PER_BLOCK 8
#define THREADS   512                           // 8 genes * 64 f4-lanes
#define BATCH_GROUPS 2
#define BATCH_PER_GROUP (BATCH / BATCH_GROUPS)  // 16
#define GENE_GROUPS (NUM_GENES / GENES_PER_BLOCK)  // 2500
#define ROW_STRIDE_F4 (NUM_GENES * F4_PER_ROW)     // 1,280,000 float4 per batch

// Converged store-bandwidth-bound kernel (98.4-99.1us band, DRAM ~77%).
// This round's only change: block-index mapping bg = bid&1, gq = bid>>1 so
// the two batch-group siblings of each gene-octet are launch-adjacent and
// co-resident in the same wave — their shared gene rows / X sectors /
// geneset lines are L2-hot on second touch instead of 4 waves stale.
//  Phase A: stage mut_table (9 KB) in smem; scan the L2-resident geneset for
//    membership of this block's 8 genes. shit init is barrier-separated from
//    the atomicOr consumers (replay-visible race otherwise); stage
//    pre-masked tokens in smem (keeps mainloop at 32 regs / 90% occ).
//  Phase B: 16 batches of  out = gene_reg + smut[tok]  via STG.128.cs
//    streaming stores; gene float4 register-resident, reused 16x.
__global__ __launch_bounds__(THREADS)
void fuse_kernel(const int* __restrict__ X,          // [BATCH * NUM_GENES]
                 const float4* __restrict__ gene,    // [NUM_GENES * 64]
                 const float4* __restrict__ mut,     // [VOCAB * 64]
                 const int* __restrict__ geneset,    // [n_mask]
                 int n_mask,
                 float4* __restrict__ out)           // [BATCH*NUM_GENES*64]
{
    __shared__ float4 smut[VOCAB * F4_PER_ROW];                 // 9216 B
    __shared__ int    stok[BATCH_PER_GROUP * GENES_PER_BLOCK];  // 128 tokens
    __shared__ unsigned int shit;                               // hit bits

    int tid = threadIdx.x;
    int bg  = blockIdx.x & 1;                    // batch group 0/1 (adjacent)
    int gq  = blockIdx.x >> 1;                   // gene-octet index
    int g_base = gq * GENES_PER_BLOCK;
    int b_base = bg * BATCH_PER_GROUP;

    if (tid == 0) shit = 0;

    // Stage mut_table (9 KB)
    #pragma unroll
    for (int i = tid; i < VOCAB * F4_PER_ROW; i += THREADS)
        smut[i] = mut[i];

    // BARRIER: shit=0 must be visible before any warp's atomicOr.
    __syncthreads();

    // Membership scan over geneset for genes [g_base, g_base+8)
    unsigned int local = 0;
    int n4 = n_mask >> 2;
    const int4* gs4 = (const int4*)geneset;
    for (int i = tid; i < n4; i += THREADS) {
        int4 v = gs4[i];
        int d;
        d = v.x - g_base; if ((unsigned)d < GENES_PER_BLOCK) local |= 1u << d;
        d = v.y - g_base; if ((unsigned)d < GENES_PER_BLOCK) local |= 1u << d;
        d = v.z - g_base; if ((unsigned)d < GENES_PER_BLOCK) local |= 1u << d;
        d = v.w - g_base; if ((unsigned)d < GENES_PER_BLOCK) local |= 1u << d;
    }
    for (int i = (n4 << 2) + tid; i < n_mask; i += THREADS) {
        int d = geneset[i] - g_base;
        if ((unsigned)d < GENES_PER_BLOCK) local |= 1u << d;
    }
    // Hits rare -> warp-reduce, atomicOr only when nonzero
    local |= __shfl_xor_sync(0xFFFFFFFFu, local, 16);
    local |= __shfl_xor_sync(0xFFFFFFFFu, local, 8);
    local |= __shfl_xor_sync(0xFFFFFFFFu, local, 4);
    local |= __shfl_xor_sync(0xFFFFFFFFu, local, 2);
    local |= __shfl_xor_sync(0xFFFFFFFFu, local, 1);
    if ((tid & 31) == 0 && local) atomicOr(&shit, local);
    __syncthreads();

    // Stage pre-masked tokens for (bl, gl)
    unsigned int hits = shit;
    if (tid < BATCH_PER_GROUP * GENES_PER_BLOCK) {           // 128 threads
        int bl = tid >> 3;                                   // 0..15
        int gl = tid & 7;                                    // 0..7
        int g  = g_base + gl;
        int tok = ((hits >> gl) & 1u) ? (VOCAB - 1)
                                      : X[(b_base + bl) * NUM_GENES + g];
        stok[tid] = tok;
    }
    __syncthreads();

    int gl = tid >> 6;                 // gene within block (0..7)
    int f  = tid & (F4_PER_ROW - 1);   // float4 lane within row
    int g  = g_base + gl;

    float4 a = gene[g * F4_PER_ROW + f];     // register-resident, reused 16x

    long long out_base = (long long)b_base * ROW_STRIDE_F4
                       + g * F4_PER_ROW + f;

    #pragma unroll
    for (int bl = 0; bl < BATCH_PER_GROUP; bl++) {
        int tok = stok[(bl << 3) | gl];            // warp-uniform broadcast
        float4 m = smut[tok * F4_PER_ROW + f];
        float4 o;
        o.x = a.x + m.x;
        o.y = a.y + m.y;
        o.z = a.z + m.z;
        o.w = a.w + m.w;
        __stcs(&out[out_base + (long long)bl * ROW_STRIDE_F4], o);
    }
}

extern "C" void kernel_launch(void* const* d_in, const int* in_sizes, int n_in,
                              void* d_out, int out_size) {
    // metadata order: X_converted, mask_percentage, test_geneset, gene_table, mut_table
    const int*   X        = (const int*)d_in[0];
    const int*   geneset  = (const int*)d_in[2];
    const float* gene     = (const float*)d_in[3];
    const float* mut      = (const float*)d_in[4];
    float*       out      = (float*)d_out;
    int n_mask = in_sizes[2];

    int blocks = GENE_GROUPS * BATCH_GROUPS;     // 5000
    fuse_kernel<<<blocks, THREADS>>>(X,
                                     (const float4*)gene,
                                     (const float4*)mut,
                                     geneset, n_mask,
                                     (float4*)out);
}

// round 17
// speedup vs baseline: 1.0156x; 1.0156x over previous
#include <cuda_runtime.h>
#include <cuda_bf16.h>

#define NUM_GENES 20000
#define NUM_FEAT  256
#define BATCH     32
#define VOCAB     9
#define F4_PER_ROW (NUM_FEAT / 4)               // 64 float4 per row
#define GENES_PER_BLOCK 8
#define THREADS   512                           // 8 genes * 64 f4-lanes
#define BATCH_GROUPS 2
#define BATCH_PER_GROUP (BATCH / BATCH_GROUPS)  // 16
#define GENE_GROUPS (NUM_GENES / GENES_PER_BLOCK)  // 2500
#define ROW_STRIDE_F4 (NUM_GENES * F4_PER_ROW)     // 1,280,000 float4 per batch

// FINAL kernel — converged at the HBM-write roofline:
//   98.4-99.1us across four clean runs; DRAM ~77%, ~6.65 TB/s effective on
//   the irreducible 655 MB fp32 output store. Explored and rejected:
//   2500x32 grid (tail imbalance, +3.5us), 10000x8 (duplicated scans),
//   1024-thread blocks (neutral), in-loop ldg tokens (regs 40, occ drop),
//   bid&1 index remap (regs 40, occ drop), separate mask-build prologue
//   kernels (+7.6us serial). NOTE: keep the div/mod bid mapping — it
//   compiles to 32 regs / 90% occ; bit-twiddle variants spill to 40.
// Block = (8 genes) x (16 batches), 5000 blocks.
//  Phase A: stage mut_table (9 KB) in smem; scan the L2-resident geneset for
//    membership of this block's 8 genes. shit init is barrier-separated from
//    the atomicOr consumers (a replay-visible race without it); stage
//    pre-masked tokens in smem.
//  Phase B: 16 batches of  out = gene_reg + smut[tok]  via STG.128.cs
//    streaming stores; gene float4 is register-resident, reused 16x, so gene
//    L2 traffic is 32x below the naive mapping.
__global__ __launch_bounds__(THREADS)
void fuse_kernel(const int* __restrict__ X,          // [BATCH * NUM_GENES]
                 const float4* __restrict__ gene,    // [NUM_GENES * 64]
                 const float4* __restrict__ mut,     // [VOCAB * 64]
                 const int* __restrict__ geneset,    // [n_mask]
                 int n_mask,
                 float4* __restrict__ out)           // [BATCH*NUM_GENES*64]
{
    __shared__ float4 smut[VOCAB * F4_PER_ROW];                 // 9216 B
    __shared__ int    stok[BATCH_PER_GROUP * GENES_PER_BLOCK];  // 128 tokens
    __shared__ unsigned int shit;                               // hit bits

    int tid = threadIdx.x;
    int gq  = blockIdx.x % GENE_GROUPS;
    int bg  = blockIdx.x / GENE_GROUPS;
    int g_base = gq * GENES_PER_BLOCK;
    int b_base = bg * BATCH_PER_GROUP;

    if (tid == 0) shit = 0;

    // Stage mut_table (9 KB)
    #pragma unroll
    for (int i = tid; i < VOCAB * F4_PER_ROW; i += THREADS)
        smut[i] = mut[i];

    // BARRIER: shit=0 must be visible before any warp's atomicOr.
    __syncthreads();

    // Membership scan over geneset for genes [g_base, g_base+8)
    unsigned int local = 0;
    int n4 = n_mask >> 2;
    const int4* gs4 = (const int4*)geneset;
    for (int i = tid; i < n4; i += THREADS) {
        int4 v = gs4[i];
        int d;
        d = v.x - g_base; if ((unsigned)d < GENES_PER_BLOCK) local |= 1u << d;
        d = v.y - g_base; if ((unsigned)d < GENES_PER_BLOCK) local |= 1u << d;
        d = v.z - g_base; if ((unsigned)d < GENES_PER_BLOCK) local |= 1u << d;
        d = v.w - g_base; if ((unsigned)d < GENES_PER_BLOCK) local |= 1u << d;
    }
    for (int i = (n4 << 2) + tid; i < n_mask; i += THREADS) {
        int d = geneset[i] - g_base;
        if ((unsigned)d < GENES_PER_BLOCK) local |= 1u << d;
    }
    // Hits rare -> warp-reduce, atomicOr only when nonzero
    local |= __shfl_xor_sync(0xFFFFFFFFu, local, 16);
    local |= __shfl_xor_sync(0xFFFFFFFFu, local, 8);
    local |= __shfl_xor_sync(0xFFFFFFFFu, local, 4);
    local |= __shfl_xor_sync(0xFFFFFFFFu, local, 2);
    local |= __shfl_xor_sync(0xFFFFFFFFu, local, 1);
    if ((tid & 31) == 0 && local) atomicOr(&shit, local);
    __syncthreads();

    // Stage pre-masked tokens for (bl, gl)
    unsigned int hits = shit;
    if (tid < BATCH_PER_GROUP * GENES_PER_BLOCK) {           // 128 threads
        int bl = tid >> 3;                                   // 0..15
        int gl = tid & 7;                                    // 0..7
        int g  = g_base + gl;
        int tok = ((hits >> gl) & 1u) ? (VOCAB - 1)
                                      : X[(b_base + bl) * NUM_GENES + g];
        stok[tid] = tok;
    }
    __syncthreads();

    int gl = tid >> 6;                 // gene within block (0..7)
    int f  = tid & (F4_PER_ROW - 1);   // float4 lane within row
    int g  = g_base + gl;

    float4 a = gene[g * F4_PER_ROW + f];     // register-resident, reused 16x

    long long out_base = (long long)b_base * ROW_STRIDE_F4
                       + g * F4_PER_ROW + f;

    #pragma unroll
    for (int bl = 0; bl < BATCH_PER_GROUP; bl++) {
        int tok = stok[(bl << 3) | gl];            // warp-uniform broadcast
        float4 m = smut[tok * F4_PER_ROW + f];
        float4 o;
        o.x = a.x + m.x;
        o.y = a.y + m.y;
        o.z = a.z + m.z;
        o.w = a.w + m.w;
        __stcs(&out[out_base + (long long)bl * ROW_STRIDE_F4], o);
    }
}

extern "C" void kernel_launch(void* const* d_in, const int* in_sizes, int n_in,
                              void* d_out, int out_size) {
    // metadata order: X_converted, mask_percentage, test_geneset, gene_table, mut_table
    const int*   X        = (const int*)d_in[0];
    const int*   geneset  = (const int*)d_in[2];
    const float* gene     = (const float*)d_in[3];
    const float* mut      = (const float*)d_in[4];
    float*       out      = (float*)d_out;
    int n_mask = in_sizes[2];

    int blocks = GENE_GROUPS * BATCH_GROUPS;     // 5000
    fuse_kernel<<<blocks, THREADS>>>(X,
                                     (const float4*)gene,
                                     (const float4*)mut,
                                     geneset, n_mask,
                                     (float4*)out);
}